// round 14
// baseline (speedup 1.0000x reference)
#include <cuda_runtime.h>
#include <cstddef>
#include <cstdint>

// Problem constants (fixed shapes): x = (256, 2048, 25, 3, 1) fp32
#define NB_ 256
#define TT 2048
#define NJ 25
#define ROW 75          // 25 joints * 3 channels, floats per frame
#define NI 57           // refined atomic intervals
#define NSL 37          // distinct sampled prefix slots (union of boundaries)
#define NCH 256         // 8-frame chunks over T=2048
#define DEP 12          // cp.async ring depth (slots)

// Chunk-index run splits (frames 680, 1360 are 8-aligned) and the interval
// index at each run start.
__constant__ int c_crun[4]   = {0, 85, 170, 256};
__constant__ int c_vstart[3] = {0, 25, 42};

// Per-chunk metadata: low 4 bits = split s (0 = no interval ends in/at the end
// of this chunk; s in [1,8]: frames with grp >= s belong to the NEXT interval,
// s == 8 = interval ends exactly at chunk end). Bit 4 = double-reduce (two
// boundaries associated with this chunk; second interval is 1-4 frames).
__constant__ unsigned char c_meta[NCH] = {
     0, 0, 0, 0, 0, 5, 0, 0, 4, 0, 0, 2, 0, 0, 0, 0,
    23, 0, 0, 0, 0, 0, 4, 0, 0, 4, 0, 0, 1, 0, 0, 0,
     0,22, 0, 0, 0, 0, 0, 3, 0, 0, 4, 0, 8, 0, 0, 0,
     0, 0,21, 0, 0, 0, 0, 0, 2, 0, 0, 4, 0, 7, 0, 0,
     0, 0, 0,20, 0, 0, 0, 0, 0, 1, 0, 0, 4, 0, 6, 0,
     0, 7, 0, 0, 8, 0, 0, 0, 0, 2, 0, 0, 0, 4, 0, 0,
     0, 6, 0, 0, 0, 8, 0, 0, 0, 0, 2, 0, 0, 0, 4, 0,
     0, 0, 6, 0, 0, 0, 8, 0, 0, 0, 0, 0, 6, 0, 0, 0,
     0, 0, 3, 0, 0, 0, 0, 8, 0, 0, 0, 0, 0, 6, 0, 0,
     0, 0, 0, 3, 0, 0, 0, 0, 8, 0, 0, 0, 0, 0, 6, 0,
     0, 0, 0, 0, 3, 0, 0, 0, 0, 8, 0, 0, 0, 0, 0, 6,
     0, 0, 0, 0, 0, 3, 0, 0, 0, 0, 8, 0, 0, 0, 0, 0,
     6, 0, 0, 0, 0, 0, 3, 0, 0, 0, 0, 8, 0, 0, 0, 0,
     0, 6, 0, 0, 0, 0, 0, 3, 0, 0, 0, 0, 8, 0, 0, 0,
     0, 0, 6, 0, 0, 0, 0, 0, 3, 0, 0, 0, 0, 8, 0, 0,
     0, 0, 0, 8, 0, 0, 0, 0, 0, 8, 0, 0, 0, 0, 0, 8};

// c_samp[i] = sample slot of boundary index i (prefix BEFORE interval i), or -1.
__constant__ signed char c_samp[NI + 1] = {
     0,  1,  2,  3,  4,  5,  6,  7,  8,  9, 10, 11, 12, 13, 14, 15,
    16, 17, 18, 19, 20, 21, 22, 23, -1, 24, -1, 25, -1, 26, -1, 27,
    -1, 28, -1, -1, 29, -1, -1, 30, -1, -1, 31, -1, -1, 32, -1, -1,
    33, -1, -1, 34, -1, -1, 35, -1, -1, 36};

// Per (u*15+g): sample slot of gaussian start / end boundary.
__constant__ unsigned char c_sslot[45] = {
    0, 5,10,15,20,24,26,28,29,30,31,32,33,34,35,      // u=0 (nb=136)
    0, 2, 5, 7,10,12,15,17,20,22,24,25,26,27,28,      // u=1 (nb=68)
    0, 1, 3, 4, 6, 8, 9,11,13,14,16,18,19,21,23};     // u=2 (nb=45)
__constant__ unsigned char c_eslot[45] = {
    5,10,15,20,24,26,28,29,30,31,32,33,34,35,36,
    2, 5, 7,10,12,15,17,20,22,24,25,26,27,28,36,
    1, 3, 4, 6, 8, 9,11,13,14,16,18,19,21,23,36};

// 1/N for body gaussians (N = nb) and tail gaussian (N = T - 14*nb).
__constant__ float c_inv_nb[3]   = {1.0f / 136.0f, 1.0f / 68.0f,   1.0f / 45.0f};
__constant__ float c_inv_tail[3] = {1.0f / 144.0f, 1.0f / 1096.0f, 1.0f / 1418.0f};

// Row entry index tables for the 4x4 augmented matrix rows (q = row).
__constant__ int c_tab[4][4] = {
    {0, 1, 2, 6}, {1, 3, 4, 7}, {2, 4, 5, 8}, {6, 7, 8, 8}};

// Phase-1 scratch: [b][interval][j*9 + e]  (13.1 MB)
__device__ float g_part[(size_t)NB_ * NI * (NJ * 9)];

// ---------------------------------------------------------------------------
// Phase 1: one block per (chunk-run, batch) -> 768 blocks ~ one wave.
// DEEP cp.async chunk-ring: 8-frame chunks (exactly 150 float4), 12-slot
// ring, issue-ahead 10 chunks (~24 KB in flight per block) so DRAM latency is
// fully hidden — the previous versions' binding defect was depth-1/2 staging
// exposing ~900 cyc per interval. Interval boundaries are handled inside the
// stream with dual accumulator sets (A = current interval, B = next) driven
// by per-chunk constant metadata; chunks span at most 2 intervals (all
// double-boundary pairs have their second boundary 8-aligned).
// ---------------------------------------------------------------------------
__global__ __launch_bounds__(256) void k_partial(const float* __restrict__ x) {
    const int qg  = blockIdx.x;     // run 0..2
    const int b   = blockIdx.y;     // batch
    const int c0  = c_crun[qg];
    const int c1  = c_crun[qg + 1];
    const int tid = threadIdx.x;
    const int j   = tid >> 3;       // joint 0..31 (25 valid)
    const int jj  = (j < NJ) ? j : 0;   // clamped for safe addressing
    const int grp = tid & 7;        // frame-within-chunk
    const bool wr = (grp == 0) && (j < NJ);

    __shared__ __align__(16) float sh[DEP * 600];   // 28.8 KB ring

    const float4* __restrict__ g4 = (const float4*)(x + (size_t)b * (TT * ROW));
    const uint32_t smbase = (uint32_t)__cvta_generic_to_shared(sh);

    int v = c_vstart[qg];           // current interval index

    // Issue chunk c into ring slot `slot` (150 float4; threads 0..149).
    // Always commits a group (empty at the tail) to keep group counting exact.
    auto issue = [&](int c, int slot) {
        if (c < c1 && tid < 150) {
            asm volatile("cp.async.cg.shared.global [%0], [%1], 16;"
                         :: "r"(smbase + (uint32_t)(slot * 600 + tid * 4) * 4u),
                            "l"(g4 + (size_t)c * 150 + tid) : "memory");
        }
        asm volatile("cp.async.commit_group;" ::: "memory");
    };

    // Prologue: DEP-1 = 11 groups in flight.
    #pragma unroll
    for (int t = 0; t < DEP - 1; ++t) issue(c0 + t, t);

    float A0=0.f,A1=0.f,A2=0.f,A3=0.f,A4=0.f,A5=0.f,A6=0.f,A7=0.f,A8=0.f;
    float B0=0.f,B1=0.f,B2=0.f,B3=0.f,B4=0.f,B5=0.f,B6=0.f,B7=0.f,B8=0.f;

    int slot  = 0;          // slot of chunk k
    int nslot = DEP - 1;    // slot for chunk k + DEP-1
    for (int k = c0; k < c1; ++k) {
        // Chunk k's group complete: issued-so-far - (DEP-2) pending allowed.
        asm volatile("cp.async.wait_group %0;" :: "n"(DEP - 2) : "memory");
        __syncthreads();    // publish chunk k; slot (k-1)%DEP free for reuse

        issue(k + DEP - 1, nslot);
        nslot = (nslot + 1 == DEP) ? 0 : nslot + 1;

        const float* p = sh + slot * 600 + 75 * grp + 3 * jj;
        slot = (slot + 1 == DEP) ? 0 : slot + 1;
        const float x0 = p[0], x1 = p[1], x2 = p[2];

        const int meta = c_meta[k];
        const int s    = meta & 15;
        const bool toB = (s > 0) && (s < 8) && (grp >= s);
        if (toB) {
            B0 += x0*x0; B1 += x0*x1; B2 += x0*x2;
            B3 += x1*x1; B4 += x1*x2; B5 += x2*x2;
            B6 += x0;    B7 += x1;    B8 += x2;
        } else {
            A0 += x0*x0; A1 += x0*x1; A2 += x0*x2;
            A3 += x1*x1; A4 += x1*x2; A5 += x2*x2;
            A6 += x0;    A7 += x1;    A8 += x2;
        }

        if (s) {
            // Reduce A over the 8-lane group and store interval v.
            #pragma unroll
            for (int d = 4; d >= 1; d >>= 1) {
                A0 += __shfl_down_sync(0xffffffffu, A0, d);
                A1 += __shfl_down_sync(0xffffffffu, A1, d);
                A2 += __shfl_down_sync(0xffffffffu, A2, d);
                A3 += __shfl_down_sync(0xffffffffu, A3, d);
                A4 += __shfl_down_sync(0xffffffffu, A4, d);
                A5 += __shfl_down_sync(0xffffffffu, A5, d);
                A6 += __shfl_down_sync(0xffffffffu, A6, d);
                A7 += __shfl_down_sync(0xffffffffu, A7, d);
                A8 += __shfl_down_sync(0xffffffffu, A8, d);
            }
            if (wr) {
                float* dst = g_part + ((size_t)b * NI + v) * (NJ * 9) + jj * 9;
                dst[0]=A0; dst[1]=A1; dst[2]=A2; dst[3]=A3; dst[4]=A4;
                dst[5]=A5; dst[6]=A6; dst[7]=A7; dst[8]=A8;
            }
            ++v;
            A0=B0; A1=B1; A2=B2; A3=B3; A4=B4; A5=B5; A6=B6; A7=B7; A8=B8;
            B0=B1=B2=B3=B4=B5=B6=B7=B8=0.f;
            if (meta & 16) {
                // Second boundary in this chunk: interval of 1-4 frames.
                #pragma unroll
                for (int d = 4; d >= 1; d >>= 1) {
                    A0 += __shfl_down_sync(0xffffffffu, A0, d);
                    A1 += __shfl_down_sync(0xffffffffu, A1, d);
                    A2 += __shfl_down_sync(0xffffffffu, A2, d);
                    A3 += __shfl_down_sync(0xffffffffu, A3, d);
                    A4 += __shfl_down_sync(0xffffffffu, A4, d);
                    A5 += __shfl_down_sync(0xffffffffu, A5, d);
                    A6 += __shfl_down_sync(0xffffffffu, A6, d);
                    A7 += __shfl_down_sync(0xffffffffu, A7, d);
                    A8 += __shfl_down_sync(0xffffffffu, A8, d);
                }
                if (wr) {
                    float* dst = g_part + ((size_t)b * NI + v) * (NJ * 9) + jj * 9;
                    dst[0]=A0; dst[1]=A1; dst[2]=A2; dst[3]=A3; dst[4]=A4;
                    dst[5]=A5; dst[6]=A6; dst[7]=A7; dst[8]=A8;
                }
                ++v;
                A0=A1=A2=A3=A4=A5=A6=A7=A8=0.f;
            }
        }
    }
}

// ---------------------------------------------------------------------------
// Phase 2: ONE block per batch (256 blocks x 512 thr). Interval prefix
// computed once (225 channel-threads, 57 unrolled L2 loads), sampled into the
// 37-slot boundary union (33.3 KB smem). Output descriptors (np,g,p,q) are
// precomputed ONCE per thread for its 3 row positions, then reused across the
// 6 segments — all index divisions hoisted out of the store loop.
// ---------------------------------------------------------------------------
__global__ __launch_bounds__(512) void k_out(float* __restrict__ out) {
    const int b   = blockIdx.x;
    const int tid = threadIdx.x;

    __shared__ __align__(16) float sP[NSL * 225];   // 33.3 KB sampled prefixes

    if (tid < NJ * 9) {
        const float* __restrict__ gp =
            g_part + (size_t)b * NI * (NJ * 9) + tid;
        float run = 0.f;
        #pragma unroll
        for (int i = 0; i < NI; ++i) {
            const int sl = c_samp[i];
            if (sl >= 0) sP[sl * 225 + tid] = run;
            run += gp[(size_t)i * (NJ * 9)];
        }
        sP[(NSL - 1) * 225 + tid] = run;   // boundary 57 (slot 36)
    }
    __syncthreads();

    // Precompute the 3 per-thread row descriptors (rem = tid + m*512 < 1500).
    int d_j9[3], d_g[3], d_q[3];
    #pragma unroll
    for (int m = 0; m < 3; ++m) {
        const int rem = tid + m * 512;
        if (rem < 1500) {
            const int o  = rem >> 2;
            const int np = o / 75;
            const int r  = o - np * 75;
            const int g  = r / 5;
            const int p  = r - g * 5;
            d_j9[m] = (np * 5 + p) * 9;
            d_g[m]  = g;
            d_q[m]  = rem & 3;
        }
    }

    float4* __restrict__ out4 = (float4*)out + (size_t)b * 9000;
    #pragma unroll
    for (int sg = 0; sg < 6; ++sg) {
        const int u = (sg == 0) ? 0 : (sg < 3 ? 1 : 2);
        #pragma unroll
        for (int m = 0; m < 3; ++m) {
            const int rem = tid + m * 512;
            if (rem < 1500) {
                const int g = d_g[m];
                const int t = u * 15 + g;
                const float invN = (g < 14) ? c_inv_nb[u] : c_inv_tail[u];
                const float* Pa = sP + (int)c_sslot[t] * 225 + d_j9[m];
                const float* Pb = sP + (int)c_eslot[t] * 225 + d_j9[m];
                const int* e = c_tab[d_q[m]];
                float4 w;
                w.x = (Pb[e[0]] - Pa[e[0]]) * invN;
                w.y = (Pb[e[1]] - Pa[e[1]]) * invN;
                w.z = (Pb[e[2]] - Pa[e[2]]) * invN;
                w.w = (d_q[m] == 3) ? 1.0f : (Pb[e[3]] - Pa[e[3]]) * invN;
                out4[sg * 1500 + rem] = w;
            }
        }
    }
}

extern "C" void kernel_launch(void* const* d_in, const int* in_sizes, int n_in,
                              void* d_out, int out_size) {
    const float* x = (const float*)d_in[0];
    float* out = (float*)d_out;
    (void)in_sizes; (void)n_in; (void)out_size;

    k_partial<<<dim3(3, NB_), 256>>>(x);
    k_out<<<NB_, 512>>>(out);
}

// round 15
// speedup vs baseline: 1.0287x; 1.0287x over previous
#include <cuda_runtime.h>
#include <cstddef>
#include <cstdint>

// Problem constants (fixed shapes): x = (256, 2048, 25, 3, 1) fp32
#define NB_ 256
#define TT 2048
#define NJ 25
#define ROW 75          // 25 joints * 3 channels, floats per frame
#define NI 57           // refined atomic intervals (all <= 48 frames)
#define MAXF 48         // largest refined interval length in frames
#define BUFN (MAXF * ROW + 4)   // 3604 floats per stage buffer
#define NSL 37          // distinct sampled prefix slots (union of boundaries)

// Refined union of gaussian chunk boundaries for nb_fr in {136, 68, 45} over
// T=2048, further split so every interval is <= 48 frames.
__constant__ int c_bound[NI + 1] = {
       0,   45,   68,   90,  135,  136,  180,  204,  225,  270,
     272,  315,  340,  360,  405,  408,  450,  476,  495,  540,
     544,  585,  612,  630,  655,  680,  714,  748,  782,  816,
     850,  884,  918,  952,  998, 1043, 1088, 1134, 1179, 1224,
    1270, 1315, 1360, 1406, 1451, 1496, 1542, 1587, 1632, 1678,
    1723, 1768, 1814, 1859, 1904, 1952, 2000, 2048};

// Interval-index splits giving 3 balanced runs (680/680/688 frames).
__constant__ int c_qsplit[4] = {0, 25, 42, 57};

// c_samp[i] = sample slot of boundary index i (prefix BEFORE interval i), or -1.
__constant__ signed char c_samp[NI + 1] = {
     0,  1,  2,  3,  4,  5,  6,  7,  8,  9, 10, 11, 12, 13, 14, 15,
    16, 17, 18, 19, 20, 21, 22, 23, -1, 24, -1, 25, -1, 26, -1, 27,
    -1, 28, -1, -1, 29, -1, -1, 30, -1, -1, 31, -1, -1, 32, -1, -1,
    33, -1, -1, 34, -1, -1, 35, -1, -1, 36};

// Per (u*15+g): sample slot of gaussian start / end boundary.
__constant__ unsigned char c_sslot[45] = {
    0, 5,10,15,20,24,26,28,29,30,31,32,33,34,35,      // u=0 (nb=136)
    0, 2, 5, 7,10,12,15,17,20,22,24,25,26,27,28,      // u=1 (nb=68)
    0, 1, 3, 4, 6, 8, 9,11,13,14,16,18,19,21,23};     // u=2 (nb=45)
__constant__ unsigned char c_eslot[45] = {
    5,10,15,20,24,26,28,29,30,31,32,33,34,35,36,
    2, 5, 7,10,12,15,17,20,22,24,25,26,27,28,36,
    1, 3, 4, 6, 8, 9,11,13,14,16,18,19,21,23,36};

// 1/N for body gaussians (N = nb) and tail gaussian (N = T - 14*nb).
__constant__ float c_inv_nb[3]   = {1.0f / 136.0f, 1.0f / 68.0f,   1.0f / 45.0f};
__constant__ float c_inv_tail[3] = {1.0f / 144.0f, 1.0f / 1096.0f, 1.0f / 1418.0f};

// Row entry index tables for the 4x4 augmented matrix rows (q = row).
__constant__ int c_tab[4][4] = {
    {0, 1, 2, 6}, {1, 3, 4, 7}, {2, 4, 5, 8}, {6, 7, 8, 8}};

// Phase-1 scratch: [b][interval][j*9 + e]  (13.1 MB)
__device__ float g_part[(size_t)NB_ * NI * (NJ * 9)];
// Per-batch arrival counters (zero-initialized; trigger block resets to 0,
// so every call — correctness, capture, each replay — sees a clean state).
__device__ int g_done[NB_];

// ---------------------------------------------------------------------------
// Fused kernel. Phase A (all 768 blocks): cp.async double-buffered interval
// staging + 9-moment reduction (best-measured structure, ~50 us). Phase B
// (last arriver per batch): output epilogue — interval prefix sampled at the
// 37-slot boundary union, all 6 segments' 9000 float4 rows written coalesced.
// g_part is L2-hot at epilogue time; no extra kernel launch, no extra wave.
// ---------------------------------------------------------------------------
__global__ __launch_bounds__(256) void k_fused(const float* __restrict__ x,
                                               float* __restrict__ out) {
    const int qg  = blockIdx.x;     // interval-run 0..2
    const int b   = blockIdx.y;     // batch
    const int i0  = c_qsplit[qg];
    const int i1  = c_qsplit[qg + 1];
    const int tid = threadIdx.x;

    // Union: phase A uses 2*BUFN=7208 floats (staging ring); phase B uses
    // NSL*225=8325 floats (sampled prefixes). 33.3 KB -> 6 blocks/SM.
    __shared__ __align__(16) float smem_u[NSL * 225];
    __shared__ float red[NJ * 9];
    __shared__ int s_trig;

    // ---------------- Phase A: partial sums ----------------
    {
        float* sh0 = smem_u;
        float* sh1 = smem_u + BUFN;
        const size_t base = (size_t)b * (TT * ROW);   // 16B-aligned per batch

        auto stage = [&](int i, int s) {
            const int t0 = c_bound[i], t1 = c_bound[i + 1];
            const int s4 = (t0 * ROW) & ~3;
            const int n4 = (t1 * ROW - s4 + 3) >> 2;
            const float* __restrict__ g = x + base + s4;
            uint32_t sm = (uint32_t)__cvta_generic_to_shared(s ? sh1 : sh0);
            for (int idx = tid; idx < n4; idx += 256) {
                asm volatile("cp.async.cg.shared.global [%0], [%1], 16;"
                             :: "r"(sm + idx * 16), "l"(g + idx * 4) : "memory");
            }
            asm volatile("cp.async.commit_group;" ::: "memory");
        };

        stage(i0, 0);
        for (int i = i0; i < i1; ++i) {
            const int s = (i - i0) & 1;
            if (i + 1 < i1) {
                stage(i + 1, s ^ 1);
                asm volatile("cp.async.wait_group 1;" ::: "memory");
            } else {
                asm volatile("cp.async.wait_group 0;" ::: "memory");
            }
            __syncthreads();

            const int t0  = c_bound[i];
            const int F   = c_bound[i + 1] - t0;
            const int pad = (t0 * ROW) & 3;

            float a0 = 0.f, a1 = 0.f, a2 = 0.f, a3 = 0.f, a4 = 0.f,
                  a5 = 0.f, a6 = 0.f, a7 = 0.f, a8 = 0.f;
            const int j   = tid >> 3;    // joint 0..31 (25 valid)
            const int grp = tid & 7;     // 8-lane frame group
            if (j < NJ) {
                const float* shp = (s ? sh1 : sh0) + pad + j * 3;
                #pragma unroll 2
                for (int f = grp; f < F; f += 8) {
                    const float* p = shp + f * ROW;
                    const float x0 = p[0], x1 = p[1], x2 = p[2];
                    a0 += x0 * x0; a1 += x0 * x1; a2 += x0 * x2;
                    a3 += x1 * x1; a4 += x1 * x2; a5 += x2 * x2;
                    a6 += x0;      a7 += x1;      a8 += x2;
                }
            }
            #pragma unroll
            for (int d = 4; d >= 1; d >>= 1) {
                a0 += __shfl_down_sync(0xffffffffu, a0, d);
                a1 += __shfl_down_sync(0xffffffffu, a1, d);
                a2 += __shfl_down_sync(0xffffffffu, a2, d);
                a3 += __shfl_down_sync(0xffffffffu, a3, d);
                a4 += __shfl_down_sync(0xffffffffu, a4, d);
                a5 += __shfl_down_sync(0xffffffffu, a5, d);
                a6 += __shfl_down_sync(0xffffffffu, a6, d);
                a7 += __shfl_down_sync(0xffffffffu, a7, d);
                a8 += __shfl_down_sync(0xffffffffu, a8, d);
            }
            if (grp == 0 && j < NJ) {
                float* r = red + j * 9;
                r[0] = a0; r[1] = a1; r[2] = a2; r[3] = a3; r[4] = a4;
                r[5] = a5; r[6] = a6; r[7] = a7; r[8] = a8;
            }
            __syncthreads();
            if (tid < NJ * 9)
                g_part[((size_t)b * NI + i) * (NJ * 9) + tid] = red[tid];
            __syncthreads();   // stage buffer s reused by stage(i+2)
        }
    }

    // ---------------- Arrival protocol ----------------
    // Make this block's g_part stores device-visible, then count arrivals.
    __threadfence();
    __syncthreads();
    if (tid == 0) {
        const int ret = atomicAdd(&g_done[b], 1);
        const int trig = (ret == 2);
        if (trig) g_done[b] = 0;     // reset for the next graph replay
        s_trig = trig;
    }
    __syncthreads();
    if (!s_trig) return;             // 2 of 3 blocks exit; last runs epilogue

    // ---------------- Phase B: output epilogue (one block per batch) -------
    float* sP = smem_u;              // reuse staging smem as sampled prefixes

    if (tid < NJ * 9) {
        const float* __restrict__ gp =
            g_part + (size_t)b * NI * (NJ * 9) + tid;
        float run = 0.f;
        #pragma unroll
        for (int i = 0; i < NI; ++i) {
            const int sl = c_samp[i];
            if (sl >= 0) sP[sl * 225 + tid] = run;
            run += gp[(size_t)i * (NJ * 9)];
        }
        sP[(NSL - 1) * 225 + tid] = run;   // boundary 57 (slot 36)
    }
    __syncthreads();

    // Precompute the 6 per-thread row descriptors (rem = tid + m*256 < 1500).
    int d_j9[6], d_g[6], d_q[6];
    #pragma unroll
    for (int m = 0; m < 6; ++m) {
        const int rem = tid + m * 256;
        if (rem < 1500) {
            const int o  = rem >> 2;
            const int np = o / 75;
            const int r  = o - np * 75;
            const int g  = r / 5;
            const int p  = r - g * 5;
            d_j9[m] = (np * 5 + p) * 9;
            d_g[m]  = g;
            d_q[m]  = rem & 3;
        }
    }

    // out shape (b, 6, 5, 15, 5, 4, 4): per (b, sg) a contiguous run of 1500
    // float4 rows in (np, g, p, q) order — fully coalesced STG.128.
    float4* __restrict__ out4 = (float4*)out + (size_t)b * 9000;
    #pragma unroll
    for (int sg = 0; sg < 6; ++sg) {
        const int u = (sg == 0) ? 0 : (sg < 3 ? 1 : 2);
        #pragma unroll
        for (int m = 0; m < 6; ++m) {
            const int rem = tid + m * 256;
            if (rem < 1500) {
                const int g = d_g[m];
                const int t = u * 15 + g;
                const float invN = (g < 14) ? c_inv_nb[u] : c_inv_tail[u];
                const float* Pa = sP + (int)c_sslot[t] * 225 + d_j9[m];
                const float* Pb = sP + (int)c_eslot[t] * 225 + d_j9[m];
                const int* e = c_tab[d_q[m]];
                float4 w;
                w.x = (Pb[e[0]] - Pa[e[0]]) * invN;
                w.y = (Pb[e[1]] - Pa[e[1]]) * invN;
                w.z = (Pb[e[2]] - Pa[e[2]]) * invN;
                w.w = (d_q[m] == 3) ? 1.0f : (Pb[e[3]] - Pa[e[3]]) * invN;
                out4[sg * 1500 + rem] = w;
            }
        }
    }
}

extern "C" void kernel_launch(void* const* d_in, const int* in_sizes, int n_in,
                              void* d_out, int out_size) {
    const float* x = (const float*)d_in[0];
    float* out = (float*)d_out;
    (void)in_sizes; (void)n_in; (void)out_size;

    k_fused<<<dim3(3, NB_), 256>>>(x, out);
}

// round 17
// speedup vs baseline: 1.1535x; 1.1212x over previous
#include <cuda_runtime.h>
#include <cstddef>
#include <cstdint>

// Problem constants (fixed shapes): x = (256, 2048, 25, 3, 1) fp32
#define NB_ 256
#define TT 2048
#define NJ 25
#define ROW 75          // 25 joints * 3 channels, floats per frame
#define NI 57           // refined atomic intervals (all <= 48 frames)
#define MAXF 48         // largest refined interval length in frames
#define BUFN (MAXF * ROW + 4)   // 3604 floats per stage buffer
#define NSL 37          // distinct sampled prefix slots (union of boundaries)

// Refined union of gaussian chunk boundaries for nb_fr in {136, 68, 45} over
// T=2048, further split so every interval is <= 48 frames.
__constant__ int c_bound[NI + 1] = {
       0,   45,   68,   90,  135,  136,  180,  204,  225,  270,
     272,  315,  340,  360,  405,  408,  450,  476,  495,  540,
     544,  585,  612,  630,  655,  680,  714,  748,  782,  816,
     850,  884,  918,  952,  998, 1043, 1088, 1134, 1179, 1224,
    1270, 1315, 1360, 1406, 1451, 1496, 1542, 1587, 1632, 1678,
    1723, 1768, 1814, 1859, 1904, 1952, 2000, 2048};

// Interval-index splits giving 3 balanced runs (680/680/688 frames).
__constant__ int c_qsplit[4] = {0, 25, 42, 57};

// c_samp[i] = sample slot of boundary index i (prefix BEFORE interval i), or -1.
__constant__ signed char c_samp[NI + 1] = {
     0,  1,  2,  3,  4,  5,  6,  7,  8,  9, 10, 11, 12, 13, 14, 15,
    16, 17, 18, 19, 20, 21, 22, 23, -1, 24, -1, 25, -1, 26, -1, 27,
    -1, 28, -1, -1, 29, -1, -1, 30, -1, -1, 31, -1, -1, 32, -1, -1,
    33, -1, -1, 34, -1, -1, 35, -1, -1, 36};

// Per (u*15+g): sample slot of gaussian start / end boundary.
__constant__ unsigned char c_sslot[45] = {
    0, 5,10,15,20,24,26,28,29,30,31,32,33,34,35,      // u=0 (nb=136)
    0, 2, 5, 7,10,12,15,17,20,22,24,25,26,27,28,      // u=1 (nb=68)
    0, 1, 3, 4, 6, 8, 9,11,13,14,16,18,19,21,23};     // u=2 (nb=45)
__constant__ unsigned char c_eslot[45] = {
    5,10,15,20,24,26,28,29,30,31,32,33,34,35,36,
    2, 5, 7,10,12,15,17,20,22,24,25,26,27,28,36,
    1, 3, 4, 6, 8, 9,11,13,14,16,18,19,21,23,36};

// 1/N for body gaussians (N = nb) and tail gaussian (N = T - 14*nb).
__constant__ float c_inv_nb[3]   = {1.0f / 136.0f, 1.0f / 68.0f,   1.0f / 45.0f};
__constant__ float c_inv_tail[3] = {1.0f / 144.0f, 1.0f / 1096.0f, 1.0f / 1418.0f};

// Row entry index tables for the 4x4 augmented matrix rows (q = row).
__constant__ int c_tab[4][4] = {
    {0, 1, 2, 6}, {1, 3, 4, 7}, {2, 4, 5, 8}, {6, 7, 8, 8}};

// Phase-1 scratch: [b][interval][j*9 + e]  (13.1 MB)
__device__ float g_part[(size_t)NB_ * NI * (NJ * 9)];

// ---------------------------------------------------------------------------
// Phase 1: one block per (interval-run, batch) -> 768 blocks, ALL resident in
// one wave at 6 blocks/SM (launch_bounds minBlocks=6 caps regs ~40; smem
// 29.8 KB/block). cp.async double-buffered interval staging. The reduction
// loop is pure pointer-bump form: one IADD per 8-frame step, no per-iteration
// index math — attacking the 3x instruction fat measured in R15's profile.
// ---------------------------------------------------------------------------
__global__ __launch_bounds__(256, 6) void k_partial(const float* __restrict__ x) {
    const int qg  = blockIdx.x;     // interval-run 0..2
    const int b   = blockIdx.y;     // batch
    const int i0  = c_qsplit[qg];
    const int i1  = c_qsplit[qg + 1];
    const int tid = threadIdx.x;

    __shared__ __align__(16) float sh[2][BUFN];   // 28.8 KB double buffer
    __shared__ float red[NJ * 9];

    const size_t base = (size_t)b * (TT * ROW);   // 16B-aligned per batch

    auto stage = [&](int i, int s) {
        const int t0 = c_bound[i], t1 = c_bound[i + 1];
        const int s4 = (t0 * ROW) & ~3;
        const int n4 = (t1 * ROW - s4 + 3) >> 2;
        const float* __restrict__ g = x + base + s4;
        uint32_t sm = (uint32_t)__cvta_generic_to_shared(sh[s]);
        #pragma unroll 4
        for (int idx = tid; idx < n4; idx += 256) {
            asm volatile("cp.async.cg.shared.global [%0], [%1], 16;"
                         :: "r"(sm + idx * 16), "l"(g + idx * 4) : "memory");
        }
        asm volatile("cp.async.commit_group;" ::: "memory");
    };

    const int j   = tid >> 3;    // joint 0..31 (25 valid)
    const int grp = tid & 7;     // 8-lane frame group
    const int jofs = j * 3 + grp * ROW;

    stage(i0, 0);
    for (int i = i0; i < i1; ++i) {
        const int s = (i - i0) & 1;
        if (i + 1 < i1) {
            stage(i + 1, s ^ 1);
            asm volatile("cp.async.wait_group 1;" ::: "memory");
        } else {
            asm volatile("cp.async.wait_group 0;" ::: "memory");
        }
        __syncthreads();

        const int t0  = c_bound[i];
        const int F   = c_bound[i + 1] - t0;
        const int pad = (t0 * ROW) & 3;

        float a0 = 0.f, a1 = 0.f, a2 = 0.f, a3 = 0.f, a4 = 0.f,
              a5 = 0.f, a6 = 0.f, a7 = 0.f, a8 = 0.f;
        if (j < NJ) {
            // Pointer-bump loop: 3 LDS + 9 FFMA + 1 IADD per frame-step.
            const float* p = sh[s] + pad + jofs;
            int it = (F - grp + 7) >> 3;     // frames for this thread (>=1)
            #pragma unroll 2
            for (; it > 0; --it) {
                const float x0 = p[0], x1 = p[1], x2 = p[2];
                p += 8 * ROW;
                a0 += x0 * x0; a1 += x0 * x1; a2 += x0 * x2;
                a3 += x1 * x1; a4 += x1 * x2; a5 += x2 * x2;
                a6 += x0;      a7 += x1;      a8 += x2;
            }
        }
        #pragma unroll
        for (int d = 4; d >= 1; d >>= 1) {
            a0 += __shfl_down_sync(0xffffffffu, a0, d);
            a1 += __shfl_down_sync(0xffffffffu, a1, d);
            a2 += __shfl_down_sync(0xffffffffu, a2, d);
            a3 += __shfl_down_sync(0xffffffffu, a3, d);
            a4 += __shfl_down_sync(0xffffffffu, a4, d);
            a5 += __shfl_down_sync(0xffffffffu, a5, d);
            a6 += __shfl_down_sync(0xffffffffu, a6, d);
            a7 += __shfl_down_sync(0xffffffffu, a7, d);
            a8 += __shfl_down_sync(0xffffffffu, a8, d);
        }
        if (grp == 0 && j < NJ) {
            float* r = red + j * 9;
            r[0] = a0; r[1] = a1; r[2] = a2; r[3] = a3; r[4] = a4;
            r[5] = a5; r[6] = a6; r[7] = a7; r[8] = a8;
        }
        __syncthreads();
        if (tid < NJ * 9)
            g_part[((size_t)b * NI + i) * (NJ * 9) + tid] = red[tid];
        __syncthreads();   // stage buffer s reused by stage(i+2)
    }
}

// ---------------------------------------------------------------------------
// Phase 2: ONE block per batch (256 blocks x 512 thr). Interval prefix
// computed once (225 channel-threads, 57 unrolled L2 loads), sampled into the
// 37-slot boundary union (33.3 KB smem). Output descriptors precomputed once
// per thread and reused across the 6 segments; coalesced STG.128 stores.
// (R14-measured: 13.5 us.)
// ---------------------------------------------------------------------------
__global__ __launch_bounds__(512) void k_out(float* __restrict__ out) {
    const int b   = blockIdx.x;
    const int tid = threadIdx.x;

    __shared__ __align__(16) float sP[NSL * 225];   // 33.3 KB sampled prefixes

    if (tid < NJ * 9) {
        const float* __restrict__ gp =
            g_part + (size_t)b * NI * (NJ * 9) + tid;
        float run = 0.f;
        #pragma unroll
        for (int i = 0; i < NI; ++i) {
            const int sl = c_samp[i];
            if (sl >= 0) sP[sl * 225 + tid] = run;
            run += gp[(size_t)i * (NJ * 9)];
        }
        sP[(NSL - 1) * 225 + tid] = run;   // boundary 57 (slot 36)
    }
    __syncthreads();

    // Precompute the 3 per-thread row descriptors (rem = tid + m*512 < 1500).
    int d_j9[3], d_g[3], d_q[3];
    #pragma unroll
    for (int m = 0; m < 3; ++m) {
        const int rem = tid + m * 512;
        if (rem < 1500) {
            const int o  = rem >> 2;
            const int np = o / 75;
            const int r  = o - np * 75;
            const int g  = r / 5;
            const int p  = r - g * 5;
            d_j9[m] = (np * 5 + p) * 9;
            d_g[m]  = g;
            d_q[m]  = rem & 3;
        }
    }

    // out shape (b, 6, 5, 15, 5, 4, 4): per (b, sg) a contiguous run of 1500
    // float4 rows in (np, g, p, q) order — fully coalesced STG.128.
    float4* __restrict__ out4 = (float4*)out + (size_t)b * 9000;
    #pragma unroll
    for (int sg = 0; sg < 6; ++sg) {
        const int u = (sg == 0) ? 0 : (sg < 3 ? 1 : 2);
        #pragma unroll
        for (int m = 0; m < 3; ++m) {
            const int rem = tid + m * 512;
            if (rem < 1500) {
                const int g = d_g[m];
                const int t = u * 15 + g;
                const float invN = (g < 14) ? c_inv_nb[u] : c_inv_tail[u];
                const float* Pa = sP + (int)c_sslot[t] * 225 + d_j9[m];
                const float* Pb = sP + (int)c_eslot[t] * 225 + d_j9[m];
                const int* e = c_tab[d_q[m]];
                float4 w;
                w.x = (Pb[e[0]] - Pa[e[0]]) * invN;
                w.y = (Pb[e[1]] - Pa[e[1]]) * invN;
                w.z = (Pb[e[2]] - Pa[e[2]]) * invN;
                w.w = (d_q[m] == 3) ? 1.0f : (Pb[e[3]] - Pa[e[3]]) * invN;
                out4[sg * 1500 + rem] = w;
            }
        }
    }
}

extern "C" void kernel_launch(void* const* d_in, const int* in_sizes, int n_in,
                              void* d_out, int out_size) {
    const float* x = (const float*)d_in[0];
    float* out = (float*)d_out;
    (void)in_sizes; (void)n_in; (void)out_size;

    k_partial<<<dim3(3, NB_), 256>>>(x);
    k_out<<<NB_, 512>>>(out);
}